// round 5
// baseline (speedup 1.0000x reference)
#include <cuda_runtime.h>
#include <cstdint>

// Problem constants
#define BSZ   16
#define NDIM  256
#define DDIM  64
#define MCOLS (NDIM * DDIM)      // 16384
#define ABATCH (NDIM * NDIM)     // 65536
#define BBATCH (NDIM * MCOLS)    // 4194304

// GEMM tiling
#define BM 128
#define BN 128
#define BK 16
#define ASTR 20    // words; A-frag LDS.64 banks verified conflict-free
#define BSTR 136   // words; B rows conflict-free

__device__ int g_len[BSZ * 3];   // per batch: L1 (A), L2 (B), L3 (tar)

// ---------------- mask helpers (dtype auto-detect) -------------------------
__device__ __forceinline__ bool mask_is_u8(const void* m) {
    return *(const unsigned int*)m == 0x01010101u;
}
__device__ __forceinline__ bool mask_at(const void* m, int idx, bool u8) {
    if (u8) return ((const unsigned char*)m)[idx] != 0;
    return ((const unsigned int*)m)[idx] != 0u;
}

__global__ void len_kernel(const void* __restrict__ Am,
                           const void* __restrict__ Bm,
                           const void* __restrict__ Tm) {
    int b = blockIdx.x;
    int tid = threadIdx.x;
    __shared__ int cnt[3];
    if (tid < 3) cnt[tid] = 0;
    __syncthreads();
    const void* base[3] = {Am, Bm, Tm};
    #pragma unroll
    for (int m = 0; m < 3; m++) {
        bool u8 = mask_is_u8(base[m]);
        int v = mask_at(base[m], b * ABATCH + tid, u8) ? 1 : 0;
        #pragma unroll
        for (int o = 16; o > 0; o >>= 1) v += __shfl_down_sync(0xffffffffu, v, o);
        if ((tid & 31) == 0) atomicAdd(&cnt[m], v);
    }
    __syncthreads();
    if (tid < 3) g_len[b * 3 + tid] = cnt[tid];
}

// ---------------------------------------------------------------------------
__device__ __forceinline__ uint32_t f2tf32(float f) {
    uint32_t r;
    asm("cvt.rna.tf32.f32 %0, %1;" : "=r"(r) : "f"(f));
    return r;
}

__device__ __forceinline__ void mma_tf32(float* c, uint32_t a0, uint32_t a1,
                                         uint32_t a2, uint32_t a3,
                                         uint32_t b0, uint32_t b1) {
    asm volatile(
        "mma.sync.aligned.m16n8k8.row.col.f32.tf32.tf32.f32 "
        "{%0,%1,%2,%3}, {%4,%5,%6,%7}, {%8,%9}, {%0,%1,%2,%3};"
        : "+f"(c[0]), "+f"(c[1]), "+f"(c[2]), "+f"(c[3])
        : "r"(a0), "r"(a1), "r"(a2), "r"(a3), "r"(b0), "r"(b1));
}

__global__ __launch_bounds__(256, 2)
void gemm_kernel(const float* __restrict__ A,
                 const float* __restrict__ Bt,
                 const void* __restrict__ tar,
                 float* __restrict__ C) {
    // A stored col-interleaved per 8-col k-block: [0,4,1,5,2,6,3,7]
    __shared__ uint32_t As[2][BM * ASTR];
    __shared__ uint32_t Bs[2][BK * BSTR];

    const int b  = blockIdx.z;
    const int m0 = blockIdx.x * BN;
    const int i0 = blockIdx.y * BM;
    const int tid = threadIdx.x;
    const int lane = tid & 31;
    const int w = tid >> 5;
    const int wm = w >> 2;      // 0..1 -> 64 rows each
    const int wn = w & 3;       // 0..3 -> 32 cols each

    const int L1 = g_len[b * 3 + 0];
    const int L2 = g_len[b * 3 + 1];
    const int Kmin = min(L1, L2);
    const int T = (Kmin + BK - 1) / BK;   // >= 8 (L >= 128)

    const float* Ab = A + b * ABATCH + i0 * NDIM;
    const float* Bb = Bt + (size_t)b * BBATCH;

    float acc[4][4][4];
    #pragma unroll
    for (int mf = 0; mf < 4; mf++)
        #pragma unroll
        for (int nf = 0; nf < 4; nf++)
            #pragma unroll
            for (int r = 0; r < 4; r++) acc[mf][nf][r] = 0.0f;

    // ---- producer coordinates ----
    // A: thread -> row = tid>>1 (0..127), ks = tid&1; loads 8 floats of that row
    const int pa_row = tid >> 1;
    const int pa_ks  = tid & 1;
    // B: 512 float4 chunks; thread handles c = tid, tid+256
    const int pb_jl0 = tid >> 5;          // 0..7 ; second chunk +8
    const int pb_col = (lane) * 4;

    float ra[8];
    float rb0[4], rb1[4];

    auto ldg = [&](int t) {
        const int k0 = t * BK;
        // A: 8 floats, always in-bounds (k0+15 <= 255); mask by Kmin
        const float* ga = Ab + pa_row * NDIM + k0 + pa_ks * 8;
        float4 v0 = *reinterpret_cast<const float4*>(ga);
        float4 v1 = *reinterpret_cast<const float4*>(ga + 4);
        ra[0] = v0.x; ra[1] = v0.y; ra[2] = v0.z; ra[3] = v0.w;
        ra[4] = v1.x; ra[5] = v1.y; ra[6] = v1.z; ra[7] = v1.w;
        const int rem = Kmin - (k0 + pa_ks * 8);
        #pragma unroll
        for (int e = 0; e < 8; e++) if (e >= rem) ra[e] = 0.0f;
        // B: rows j = k0 + jl (always < 256)
        {
            int j = k0 + pb_jl0;
            float4 v = *reinterpret_cast<const float4*>(Bb + (size_t)j * MCOLS + m0 + pb_col);
            bool ok = (j < Kmin);
            rb0[0] = ok ? v.x : 0.f; rb0[1] = ok ? v.y : 0.f;
            rb0[2] = ok ? v.z : 0.f; rb0[3] = ok ? v.w : 0.f;
        }
        {
            int j = k0 + pb_jl0 + 8;
            float4 v = *reinterpret_cast<const float4*>(Bb + (size_t)j * MCOLS + m0 + pb_col);
            bool ok = (j < Kmin);
            rb1[0] = ok ? v.x : 0.f; rb1[1] = ok ? v.y : 0.f;
            rb1[2] = ok ? v.z : 0.f; rb1[3] = ok ? v.w : 0.f;
        }
    };

    auto sts = [&](int s) {
        // A: permute cols [0,4,1,5,2,6,3,7], two STS.128
        uint32_t* pa = &As[s][pa_row * ASTR + pa_ks * 8];
        uint4 u0 = make_uint4(f2tf32(ra[0]), f2tf32(ra[4]), f2tf32(ra[1]), f2tf32(ra[5]));
        uint4 u1 = make_uint4(f2tf32(ra[2]), f2tf32(ra[6]), f2tf32(ra[3]), f2tf32(ra[7]));
        *reinterpret_cast<uint4*>(pa)     = u0;
        *reinterpret_cast<uint4*>(pa + 4) = u1;
        // B: row-major K x N
        uint32_t* pb0 = &Bs[s][pb_jl0 * BSTR + pb_col];
        *reinterpret_cast<uint4*>(pb0) =
            make_uint4(f2tf32(rb0[0]), f2tf32(rb0[1]), f2tf32(rb0[2]), f2tf32(rb0[3]));
        uint32_t* pb1 = &Bs[s][(pb_jl0 + 8) * BSTR + pb_col];
        *reinterpret_cast<uint4*>(pb1) =
            make_uint4(f2tf32(rb1[0]), f2tf32(rb1[1]), f2tf32(rb1[2]), f2tf32(rb1[3]));
    };

    ldg(0);

    for (int t = 0; t < T; t++) {
        const int s = t & 1;
        sts(s);
        __syncthreads();
        if (t + 1 < T) ldg(t + 1);

        #pragma unroll
        for (int ks = 0; ks < 2; ks++) {
            uint32_t a0[4], a1[4], a2[4], a3[4];
            uint32_t b0[4], b1[4];
            #pragma unroll
            for (int mf = 0; mf < 4; mf++) {
                const uint32_t* p = &As[s][(wm * 64 + mf * 16 + (lane >> 2)) * ASTR
                                           + ks * 8 + (lane & 3) * 2];
                uint2 p02 = *reinterpret_cast<const uint2*>(p);            // (a0, a2)
                uint2 p13 = *reinterpret_cast<const uint2*>(p + 8 * ASTR); // (a1, a3)
                a0[mf] = p02.x; a2[mf] = p02.y;
                a1[mf] = p13.x; a3[mf] = p13.y;
            }
            #pragma unroll
            for (int nf = 0; nf < 4; nf++) {
                const uint32_t* p = &Bs[s][(ks * 8 + (lane & 3)) * BSTR
                                           + wn * 32 + nf * 8 + (lane >> 2)];
                b0[nf] = p[0];
                b1[nf] = p[4 * BSTR];
            }
            #pragma unroll
            for (int mf = 0; mf < 4; mf++)
                #pragma unroll
                for (int nf = 0; nf < 4; nf++)
                    mma_tf32(acc[mf][nf], a0[mf], a1[mf], a2[mf], a3[mf],
                             b0[nf], b1[nf]);
        }
        __syncthreads();   // stage s fully consumed before t+2 overwrites it
    }

    // ---- epilogue: each warp's 32-column span lies inside a single k ----
    const bool u8 = mask_is_u8(tar);
    const int kcol = (m0 >> 6) + (wn >> 1);
    const bool vcol = (kcol < L2);

    bool rmask[4][2];
    #pragma unroll
    for (int mf = 0; mf < 4; mf++) {
        #pragma unroll
        for (int h = 0; h < 2; h++) {
            int i = i0 + wm * 64 + mf * 16 + (lane >> 2) + h * 8;
            rmask[mf][h] = vcol && (i < L1)
                           && mask_at(tar, b * ABATCH + i * NDIM + kcol, u8);
        }
    }

    float* Cb = C + (size_t)b * BBATCH;
    #pragma unroll
    for (int mf = 0; mf < 4; mf++) {
        int row = i0 + wm * 64 + mf * 16 + (lane >> 2);
        #pragma unroll
        for (int nf = 0; nf < 4; nf++) {
            int col = m0 + wn * 32 + nf * 8 + (lane & 3) * 2;
            float2 v0 = rmask[mf][0] ? make_float2(acc[mf][nf][0], acc[mf][nf][1])
                                     : make_float2(0.0f, 0.0f);
            float2 v1 = rmask[mf][1] ? make_float2(acc[mf][nf][2], acc[mf][nf][3])
                                     : make_float2(0.0f, 0.0f);
            *reinterpret_cast<float2*>(Cb + (size_t)row * MCOLS + col) = v0;
            *reinterpret_cast<float2*>(Cb + (size_t)(row + 8) * MCOLS + col) = v1;
        }
    }
}

// ---------------------------------------------------------------------------
extern "C" void kernel_launch(void* const* d_in, const int* in_sizes, int n_in,
                              void* d_out, int out_size) {
    (void)in_sizes; (void)n_in; (void)out_size;
    const float* A  = (const float*)d_in[0];
    const void*  Am = d_in[1];
    const float* Bt = (const float*)d_in[2];
    const void*  Bm = d_in[3];
    const void*  Tm = d_in[4];
    float* C = (float*)d_out;

    len_kernel<<<BSZ, 256>>>(Am, Bm, Tm);

    dim3 grid(MCOLS / BN, NDIM / BM, BSZ);
    gemm_kernel<<<grid, 256>>>(A, Bt, Tm, C);
}

// round 6
// speedup vs baseline: 1.1248x; 1.1248x over previous
#include <cuda_runtime.h>
#include <cstdint>

// Problem constants
#define BSZ   16
#define NDIM  256
#define DDIM  64
#define MCOLS (NDIM * DDIM)      // 16384
#define ABATCH (NDIM * NDIM)     // 65536
#define BBATCH (NDIM * MCOLS)    // 4194304

// GEMM tiling: block 128(M) x 256(N), 8 warps of 64x64
#define BM 128
#define BN 256
#define BK 16
#define STAGES 3
#define ASTR 20     // words, BK+4 pad
#define BSTR 264    // words, BN+8 pad
#define A_ST (BM * ASTR)   // 2560 words
#define B_ST (BK * BSTR)   // 4224 words
#define SMEM_WORDS (STAGES * (A_ST + B_ST))
#define SMEM_BYTES (SMEM_WORDS * 4)          // 81408 B

__device__ int g_len[BSZ * 3];   // per batch: L1 (A), L2 (B), L3 (tar)

// ---------------- mask helpers (dtype auto-detect) -------------------------
__device__ __forceinline__ bool mask_is_u8(const void* m) {
    return *(const unsigned int*)m == 0x01010101u;
}
__device__ __forceinline__ bool mask_at(const void* m, int idx, bool u8) {
    if (u8) return ((const unsigned char*)m)[idx] != 0;
    return ((const unsigned int*)m)[idx] != 0u;
}

__global__ void len_kernel(const void* __restrict__ Am,
                           const void* __restrict__ Bm,
                           const void* __restrict__ Tm) {
    int b = blockIdx.x;
    int tid = threadIdx.x;
    __shared__ int cnt[3];
    if (tid < 3) cnt[tid] = 0;
    __syncthreads();
    const void* base[3] = {Am, Bm, Tm};
    #pragma unroll
    for (int m = 0; m < 3; m++) {
        bool u8 = mask_is_u8(base[m]);
        int v = mask_at(base[m], b * ABATCH + tid, u8) ? 1 : 0;
        #pragma unroll
        for (int o = 16; o > 0; o >>= 1) v += __shfl_down_sync(0xffffffffu, v, o);
        if ((tid & 31) == 0) atomicAdd(&cnt[m], v);
    }
    __syncthreads();
    if (tid < 3) g_len[b * 3 + tid] = cnt[tid];
}

// ---------------------------------------------------------------------------
__device__ __forceinline__ void cp_async16(uint32_t smem_addr, const void* gmem,
                                           int src_bytes) {
    asm volatile("cp.async.cg.shared.global [%0], [%1], 16, %2;\n"
                 :: "r"(smem_addr), "l"(gmem), "r"(src_bytes));
}
__device__ __forceinline__ uint32_t smem_u32(const void* p) {
    uint32_t a;
    asm("{ .reg .u64 t; cvta.to.shared.u64 t, %1; cvt.u32.u64 %0, t; }" : "=r"(a) : "l"(p));
    return a;
}
__device__ __forceinline__ uint32_t f2tf32(float f) {
    uint32_t r;
    asm("cvt.rna.tf32.f32 %0, %1;" : "=r"(r) : "f"(f));
    return r;
}
__device__ __forceinline__ void mma_tf32(float* c, uint32_t a0, uint32_t a1,
                                         uint32_t a2, uint32_t a3,
                                         uint32_t b0, uint32_t b1) {
    asm volatile(
        "mma.sync.aligned.m16n8k8.row.col.f32.tf32.tf32.f32 "
        "{%0,%1,%2,%3}, {%4,%5,%6,%7}, {%8,%9}, {%0,%1,%2,%3};"
        : "+f"(c[0]), "+f"(c[1]), "+f"(c[2]), "+f"(c[3])
        : "r"(a0), "r"(a1), "r"(a2), "r"(a3), "r"(b0), "r"(b1));
}

__global__ __launch_bounds__(256, 1)
void gemm_kernel(const float* __restrict__ A,
                 const float* __restrict__ Bt,
                 const void* __restrict__ tar,
                 float* __restrict__ C) {
    extern __shared__ float smem[];
    float* As[STAGES];
    float* Bs[STAGES];
    #pragma unroll
    for (int s = 0; s < STAGES; s++) {
        As[s] = smem + s * A_ST;
        Bs[s] = smem + STAGES * A_ST + s * B_ST;
    }

    const int b  = blockIdx.z;
    const int m0 = blockIdx.x * BN;
    const int i0 = blockIdx.y * BM;
    const int tid = threadIdx.x;
    const int lane = tid & 31;
    const int w = tid >> 5;
    const int wm = w >> 2;      // 0..1 -> 64 rows
    const int wn = w & 3;       // 0..3 -> 64 cols
    const int g = lane >> 2;    // 0..7
    const int r = lane & 3;     // 0..3

    const int L1 = g_len[b * 3 + 0];
    const int L2 = g_len[b * 3 + 1];
    const int Kmin = min(L1, L2);
    const int T = (Kmin + BK - 1) / BK;   // >= 8

    const float* Ab = A + b * ABATCH + i0 * NDIM;
    const float* Bb = Bt + (size_t)b * BBATCH;

    float acc[4][8][4];
    #pragma unroll
    for (int mf = 0; mf < 4; mf++)
        #pragma unroll
        for (int nf = 0; nf < 8; nf++)
            #pragma unroll
            for (int q = 0; q < 4; q++) acc[mf][nf][q] = 0.0f;

    // producer coords
    const int pa_row = tid >> 2;           // + 64 for 2nd chunk
    const int pa_col = (tid & 3) * 4;
    const int pb_row = tid >> 6;           // + 4*r for 4 chunks
    const int pb_col = (tid & 63) * 4;

    auto issue = [&](int t, int s) {
        const int k0 = t * BK;
        const uint32_t abase = smem_u32(As[s]);
        const uint32_t bbase = smem_u32(Bs[s]);
        // A: 512 chunks / 256 threads
        {
            int nfv = Kmin - (k0 + pa_col);
            nfv = nfv < 0 ? 0 : (nfv > 4 ? 4 : nfv);
            #pragma unroll
            for (int q = 0; q < 2; q++) {
                int row = pa_row + q * 64;
                cp_async16(abase + (row * ASTR + pa_col) * 4,
                           Ab + row * NDIM + k0 + pa_col, nfv * 4);
            }
        }
        // B: 1024 chunks / 256 threads
        #pragma unroll
        for (int q = 0; q < 4; q++) {
            int row = pb_row + q * 4;
            int j = k0 + row;
            cp_async16(bbase + (row * BSTR + pb_col) * 4,
                       Bb + (size_t)j * MCOLS + m0 + pb_col,
                       (j < Kmin) ? 16 : 0);
        }
        asm volatile("cp.async.commit_group;\n" ::: "memory");
    };

    issue(0, 0);
    issue(1, 1);

    for (int t = 0; t < T; t++) {
        const int s = t % STAGES;
        if (t + 1 < T) {
            asm volatile("cp.async.wait_group 1;\n" ::: "memory");
        } else {
            asm volatile("cp.async.wait_group 0;\n" ::: "memory");
        }
        __syncthreads();   // stage s data visible to all; stage (t-1)%S free for reuse

        const float* Aw = &As[s][(wm * 64 + g) * ASTR + r];
        const float* Bw = &Bs[s][r * BSTR + wn * 64 + g];

        #pragma unroll
        for (int ks = 0; ks < 2; ks++) {
            uint32_t a0[4], a1[4], a2[4], a3[4];
            uint32_t b0[8], b1[8];
            #pragma unroll
            for (int mf = 0; mf < 4; mf++) {
                const float* p = Aw + mf * 16 * ASTR + ks * 8;
                a0[mf] = f2tf32(p[0]);
                a1[mf] = f2tf32(p[8 * ASTR]);
                a2[mf] = f2tf32(p[4]);
                a3[mf] = f2tf32(p[8 * ASTR + 4]);
            }
            #pragma unroll
            for (int nf = 0; nf < 8; nf++) {
                const float* p = Bw + ks * 8 * BSTR + nf * 8;
                b0[nf] = f2tf32(p[0]);
                b1[nf] = f2tf32(p[4 * BSTR]);
            }
            #pragma unroll
            for (int mf = 0; mf < 4; mf++)
                #pragma unroll
                for (int nf = 0; nf < 8; nf++)
                    mma_tf32(acc[mf][nf], a0[mf], a1[mf], a2[mf], a3[mf],
                             b0[nf], b1[nf]);
        }

        if (t + 2 < T) issue(t + 2, (t + 2) % STAGES);  // overwrites stage (t-1)%S: safe
    }

    // ---- epilogue: warp covers 64 rows x 64 cols -> single kcol ----
    const bool u8 = mask_is_u8(tar);
    const int kcol = (m0 >> 6) + wn;
    const bool vcol = (kcol < L2);

    bool rmask[4][2];
    #pragma unroll
    for (int mf = 0; mf < 4; mf++) {
        #pragma unroll
        for (int h = 0; h < 2; h++) {
            int i = i0 + wm * 64 + mf * 16 + g + h * 8;
            rmask[mf][h] = vcol && (i < L1)
                           && mask_at(tar, b * ABATCH + i * NDIM + kcol, u8);
        }
    }

    float* Cb = C + (size_t)b * BBATCH;
    #pragma unroll
    for (int mf = 0; mf < 4; mf++) {
        int row = i0 + wm * 64 + mf * 16 + g;
        #pragma unroll
        for (int nf = 0; nf < 8; nf++) {
            int col = m0 + wn * 64 + nf * 8 + r * 2;
            float2 v0 = rmask[mf][0] ? make_float2(acc[mf][nf][0], acc[mf][nf][1])
                                     : make_float2(0.0f, 0.0f);
            float2 v1 = rmask[mf][1] ? make_float2(acc[mf][nf][2], acc[mf][nf][3])
                                     : make_float2(0.0f, 0.0f);
            *reinterpret_cast<float2*>(Cb + (size_t)row * MCOLS + col) = v0;
            *reinterpret_cast<float2*>(Cb + (size_t)(row + 8) * MCOLS + col) = v1;
        }
    }
}

// ---------------------------------------------------------------------------
extern "C" void kernel_launch(void* const* d_in, const int* in_sizes, int n_in,
                              void* d_out, int out_size) {
    (void)in_sizes; (void)n_in; (void)out_size;
    const float* A  = (const float*)d_in[0];
    const void*  Am = d_in[1];
    const float* Bt = (const float*)d_in[2];
    const void*  Bm = d_in[3];
    const void*  Tm = d_in[4];
    float* C = (float*)d_out;

    cudaFuncSetAttribute(gemm_kernel,
                         cudaFuncAttributeMaxDynamicSharedMemorySize, SMEM_BYTES);

    len_kernel<<<BSZ, 256>>>(Am, Bm, Tm);

    dim3 grid(MCOLS / BN, NDIM / BM, BSZ);
    gemm_kernel<<<grid, 256, SMEM_BYTES>>>(A, Bt, Tm, C);
}

// round 7
// speedup vs baseline: 1.6031x; 1.4251x over previous
#include <cuda_runtime.h>
#include <cstdint>

// Problem constants
#define BSZ   16
#define NDIM  256
#define DDIM  64
#define MCOLS (NDIM * DDIM)      // 16384
#define ABATCH (NDIM * NDIM)     // 65536
#define BBATCH (NDIM * MCOLS)    // 4194304

// GEMM tiling: block 128x128, 8 warps of 64x32, fp16 MMA m16n8k16
#define BM 128
#define BN 128
#define BK 32
#define ASTR 40     // words: A LDS.64 frag loads conflict-free (8g+2r pattern)
#define BSTR 132    // words: B LDS.32 frag loads conflict-free (8r+g pattern)
#define A_ST (BM * ASTR)   // 5120 words
#define B_ST (BK * BSTR)   // 4224 words
#define SMEM_WORDS (2 * (A_ST + B_ST))
#define SMEM_BYTES (SMEM_WORDS * 4)          // 74752 B

__device__ int g_len[BSZ * 3];   // per batch: L1 (A), L2 (B), L3 (tar)

// ---------------- mask helpers (dtype auto-detect) -------------------------
__device__ __forceinline__ bool mask_is_u8(const void* m) {
    return *(const unsigned int*)m == 0x01010101u;
}
__device__ __forceinline__ bool mask_at(const void* m, int idx, bool u8) {
    if (u8) return ((const unsigned char*)m)[idx] != 0;
    return ((const unsigned int*)m)[idx] != 0u;
}

__global__ void len_kernel(const void* __restrict__ Am,
                           const void* __restrict__ Bm,
                           const void* __restrict__ Tm) {
    int b = blockIdx.x;
    int tid = threadIdx.x;
    __shared__ int cnt[3];
    if (tid < 3) cnt[tid] = 0;
    __syncthreads();
    const void* base[3] = {Am, Bm, Tm};
    #pragma unroll
    for (int m = 0; m < 3; m++) {
        bool u8 = mask_is_u8(base[m]);
        int v = mask_at(base[m], b * ABATCH + tid, u8) ? 1 : 0;
        #pragma unroll
        for (int o = 16; o > 0; o >>= 1) v += __shfl_down_sync(0xffffffffu, v, o);
        if ((tid & 31) == 0) atomicAdd(&cnt[m], v);
    }
    __syncthreads();
    if (tid < 3) g_len[b * 3 + tid] = cnt[tid];
}

// ---------------------------------------------------------------------------
__device__ __forceinline__ void cp_async16(uint32_t smem_addr, const void* gmem,
                                           int src_bytes) {
    asm volatile("cp.async.cg.shared.global [%0], [%1], 16, %2;\n"
                 :: "r"(smem_addr), "l"(gmem), "r"(src_bytes));
}
__device__ __forceinline__ uint32_t smem_u32(const void* p) {
    uint32_t a;
    asm("{ .reg .u64 t; cvta.to.shared.u64 t, %1; cvt.u32.u64 %0, t; }" : "=r"(a) : "l"(p));
    return a;
}
// pack two f32 -> f16x2 (lo = first arg, hi = second)
__device__ __forceinline__ uint32_t pack_h2(float lo, float hi) {
    uint32_t d;
    asm("cvt.rn.f16x2.f32 %0, %1, %2;" : "=r"(d) : "f"(hi), "f"(lo));
    return d;
}
__device__ __forceinline__ void mma_f16(float* c, uint32_t a0, uint32_t a1,
                                        uint32_t a2, uint32_t a3,
                                        uint32_t b0, uint32_t b1) {
    asm volatile(
        "mma.sync.aligned.m16n8k16.row.col.f32.f16.f16.f32 "
        "{%0,%1,%2,%3}, {%4,%5,%6,%7}, {%8,%9}, {%0,%1,%2,%3};"
        : "+f"(c[0]), "+f"(c[1]), "+f"(c[2]), "+f"(c[3])
        : "r"(a0), "r"(a1), "r"(a2), "r"(a3), "r"(b0), "r"(b1));
}

__global__ __launch_bounds__(256, 2)
void gemm_kernel(const float* __restrict__ A,
                 const float* __restrict__ Bt,
                 const void* __restrict__ tar,
                 float* __restrict__ C) {
    extern __shared__ float smem[];
    float* As[2] = {smem, smem + A_ST};
    float* Bs[2] = {smem + 2 * A_ST, smem + 2 * A_ST + B_ST};

    const int b  = blockIdx.z;
    const int m0 = blockIdx.x * BN;
    const int i0 = blockIdx.y * BM;
    const int tid = threadIdx.x;
    const int lane = tid & 31;
    const int w = tid >> 5;
    const int wm = w >> 2;      // 0..1 -> 64 rows
    const int wn = w & 3;       // 0..3 -> 32 cols
    const int g = lane >> 2;    // 0..7
    const int r = lane & 3;     // 0..3

    const int L1 = g_len[b * 3 + 0];
    const int L2 = g_len[b * 3 + 1];
    const int Kmin = min(L1, L2);
    const int T = (Kmin + BK - 1) / BK;   // >= 4

    const float* Ab = A + b * ABATCH + i0 * NDIM;
    const float* Bb = Bt + (size_t)b * BBATCH;

    float acc[4][4][4];
    #pragma unroll
    for (int mf = 0; mf < 4; mf++)
        #pragma unroll
        for (int nf = 0; nf < 4; nf++)
            #pragma unroll
            for (int q = 0; q < 4; q++) acc[mf][nf][q] = 0.0f;

    // producer coords
    const int pa_row = tid >> 3;           // 0..31, + 32q
    const int pa_col = (tid & 7) * 4;      // 0..28
    const int pb_row = tid >> 5;           // 0..7, + 8q
    const int pb_col = (tid & 31) * 4;     // 0..124

    auto issue = [&](int t, int s) {
        const int k0 = t * BK;
        const uint32_t abase = smem_u32(As[s]);
        const uint32_t bbase = smem_u32(Bs[s]);
        int nfv = Kmin - (k0 + pa_col);
        nfv = nfv < 0 ? 0 : (nfv > 4 ? 4 : nfv);
        #pragma unroll
        for (int q = 0; q < 4; q++) {
            int row = pa_row + q * 32;
            cp_async16(abase + (row * ASTR + pa_col) * 4,
                       Ab + row * NDIM + k0 + pa_col, nfv * 4);
        }
        #pragma unroll
        for (int q = 0; q < 4; q++) {
            int row = pb_row + q * 8;
            int j = k0 + row;
            cp_async16(bbase + (row * BSTR + pb_col) * 4,
                       Bb + (size_t)j * MCOLS + m0 + pb_col,
                       (j < Kmin) ? 16 : 0);
        }
        asm volatile("cp.async.commit_group;\n" ::: "memory");
    };

    issue(0, 0);

    for (int t = 0; t < T; t++) {
        const int s = t & 1;
        if (t + 1 < T) {
            issue(t + 1, s ^ 1);
            asm volatile("cp.async.wait_group 1;\n" ::: "memory");
        } else {
            asm volatile("cp.async.wait_group 0;\n" ::: "memory");
        }
        __syncthreads();

        const float* Aw = &As[s][(wm * 64 + g) * ASTR + 2 * r];
        const float* Bw = &Bs[s][(2 * r) * BSTR + wn * 32 + g];

        #pragma unroll
        for (int ks = 0; ks < 2; ks++) {          // two k16 steps
            uint32_t a0[4], a1[4], a2[4], a3[4];
            uint32_t b0[4], b1[4];
            #pragma unroll
            for (int mf = 0; mf < 4; mf++) {
                const float* p = Aw + mf * 16 * ASTR + ks * 16;
                float2 v;
                v = *reinterpret_cast<const float2*>(p);
                a0[mf] = pack_h2(v.x, v.y);
                v = *reinterpret_cast<const float2*>(p + 8 * ASTR);
                a1[mf] = pack_h2(v.x, v.y);
                v = *reinterpret_cast<const float2*>(p + 8);
                a2[mf] = pack_h2(v.x, v.y);
                v = *reinterpret_cast<const float2*>(p + 8 * ASTR + 8);
                a3[mf] = pack_h2(v.x, v.y);
            }
            #pragma unroll
            for (int nf = 0; nf < 4; nf++) {
                const float* p = Bw + ks * 16 * BSTR + nf * 8;
                b0[nf] = pack_h2(p[0], p[BSTR]);
                b1[nf] = pack_h2(p[8 * BSTR], p[9 * BSTR]);
            }
            #pragma unroll
            for (int mf = 0; mf < 4; mf++)
                #pragma unroll
                for (int nf = 0; nf < 4; nf++)
                    mma_f16(acc[mf][nf], a0[mf], a1[mf], a2[mf], a3[mf],
                            b0[nf], b1[nf]);
        }
        __syncthreads();
    }

    // ---- epilogue: warp covers 64 rows x 32 cols -> single kcol ----
    const bool u8 = mask_is_u8(tar);
    const int kcol = (m0 >> 6) + (wn >> 1);
    const bool vcol = (kcol < L2);

    bool rmask[4][2];
    #pragma unroll
    for (int mf = 0; mf < 4; mf++) {
        #pragma unroll
        for (int h = 0; h < 2; h++) {
            int i = i0 + wm * 64 + mf * 16 + g + h * 8;
            rmask[mf][h] = vcol && (i < L1)
                           && mask_at(tar, b * ABATCH + i * NDIM + kcol, u8);
        }
    }

    float* Cb = C + (size_t)b * BBATCH;
    #pragma unroll
    for (int mf = 0; mf < 4; mf++) {
        int row = i0 + wm * 64 + mf * 16 + g;
        #pragma unroll
        for (int nf = 0; nf < 4; nf++) {
            int col = m0 + wn * 32 + nf * 8 + r * 2;
            float2 v0 = rmask[mf][0] ? make_float2(acc[mf][nf][0], acc[mf][nf][1])
                                     : make_float2(0.0f, 0.0f);
            float2 v1 = rmask[mf][1] ? make_float2(acc[mf][nf][2], acc[mf][nf][3])
                                     : make_float2(0.0f, 0.0f);
            *reinterpret_cast<float2*>(Cb + (size_t)row * MCOLS + col) = v0;
            *reinterpret_cast<float2*>(Cb + (size_t)(row + 8) * MCOLS + col) = v1;
        }
    }
}

// ---------------------------------------------------------------------------
extern "C" void kernel_launch(void* const* d_in, const int* in_sizes, int n_in,
                              void* d_out, int out_size) {
    (void)in_sizes; (void)n_in; (void)out_size;
    const float* A  = (const float*)d_in[0];
    const void*  Am = d_in[1];
    const float* Bt = (const float*)d_in[2];
    const void*  Bm = d_in[3];
    const void*  Tm = d_in[4];
    float* C = (float*)d_out;

    cudaFuncSetAttribute(gemm_kernel,
                         cudaFuncAttributeMaxDynamicSharedMemorySize, SMEM_BYTES);

    len_kernel<<<BSZ, 256>>>(Am, Bm, Tm);

    dim3 grid(MCOLS / BN, NDIM / BM, BSZ);
    gemm_kernel<<<grid, 256, SMEM_BYTES>>>(A, Bt, Tm, C);
}